// round 8
// baseline (speedup 1.0000x reference)
#include <cuda_runtime.h>
#include <cuda_fp16.h>
#include <cstdint>

#define BATCH 256
#define CCH   256       // C
#define LSQ   512       // L
#define TWOC  512       // 2C
#define KTOT  256

// ---------------------------------------------------------------------------
// Device scratch
// ---------------------------------------------------------------------------
// A paired per m-tile: [8][64][256]; rows r<32 -> W1 ch mt*32+r, r>=32 -> W2 same ch
__device__ __half  g_A[8 * 64 * KTOT];                  // 256 KB
__device__ __half  g_xh[(size_t)BATCH * LSQ * CCH];     // 67 MB  [b, l, c]

// ---------------------------------------------------------------------------
// helpers
// ---------------------------------------------------------------------------
__device__ __forceinline__ uint32_t s2u(const void* p) {
    uint32_t a;
    asm("{ .reg .u64 t; cvta.to.shared.u64 t, %1; cvt.u32.u64 %0, t; }" : "=r"(a) : "l"(p));
    return a;
}
__device__ __forceinline__ void cpasync16(uint32_t dst, const void* src) {
    asm volatile("cp.async.cg.shared.global [%0], [%1], 16;" :: "r"(dst), "l"(src) : "memory");
}
__device__ __forceinline__ void cp_commit() {
    asm volatile("cp.async.commit_group;" ::: "memory");
}
__device__ __forceinline__ void cp_wait1() {
    asm volatile("cp.async.wait_group 1;" ::: "memory");
}
__device__ __forceinline__ void cp_wait0() {
    asm volatile("cp.async.wait_group 0;" ::: "memory");
}
__device__ __forceinline__ void ldm_x4(uint32_t* r, uint32_t addr) {
    asm volatile("ldmatrix.sync.aligned.m8n8.x4.shared.b16 {%0,%1,%2,%3}, [%4];"
                 : "=r"(r[0]), "=r"(r[1]), "=r"(r[2]), "=r"(r[3]) : "r"(addr));
}
__device__ __forceinline__ void mma_f16(float* c, const uint32_t* a, uint32_t b0, uint32_t b1) {
    asm volatile(
        "mma.sync.aligned.m16n8k16.row.col.f32.f16.f16.f32 "
        "{%0,%1,%2,%3}, {%4,%5,%6,%7}, {%8,%9}, {%0,%1,%2,%3};"
        : "+f"(c[0]), "+f"(c[1]), "+f"(c[2]), "+f"(c[3])
        : "r"(a[0]), "r"(a[1]), "r"(a[2]), "r"(a[3]), "r"(b0), "r"(b1));
}

// ---------------------------------------------------------------------------
// Kernel 1: pack A paired  [8][64][256] fp16
// ---------------------------------------------------------------------------
__global__ void prep_kernel(const float* __restrict__ W) {
    int i = blockIdx.x * blockDim.x + threadIdx.x;
    if (i >= 8 * 64 * KTOT) return;
    int t = i >> 14;                 // /(64*256)
    int r = (i >> 8) & 63;
    int k = i & 255;
    int ch = t * 32 + (r & 31);
    float w = (r < 32) ? W[ch * TWOC + k] : W[ch * TWOC + CCH + k];
    g_A[i] = __float2half(w);
}

// ---------------------------------------------------------------------------
// Kernel 2: transpose + convert x[b,c,l] f32 -> xh[b,l,c] fp16
// ---------------------------------------------------------------------------
__global__ __launch_bounds__(256)
void conv_kernel(const float* __restrict__ x) {
    __shared__ float tile[128][33];
    int b  = blockIdx.z;
    int l0 = blockIdx.x * 32;
    int c0 = blockIdx.y * 128;
    int lane = threadIdx.x & 31, w = threadIdx.x >> 5;

    const float* xb = x + ((size_t)b * CCH + c0) * LSQ + l0;
#pragma unroll
    for (int i = 0; i < 16; i++) {
        int c = w + i * 8;
        tile[c][lane] = xb[(size_t)c * LSQ + lane];
    }
    __syncthreads();

#pragma unroll
    for (int i = 0; i < 4; i++) {
        int l = w + i * 8;
        int c4 = lane * 4;
        __half2 h01 = __floats2half2_rn(tile[c4 + 0][l], tile[c4 + 1][l]);
        __half2 h23 = __floats2half2_rn(tile[c4 + 2][l], tile[c4 + 3][l]);
        size_t o = ((size_t)b * LSQ + l0 + l) * CCH + c0 + c4;
        *(uint2*)(g_xh + o) = make_uint2(*(uint32_t*)&h01, *(uint32_t*)&h23);
    }
}

// ---------------------------------------------------------------------------
// Kernel 3: fused GEMM + gather + InstanceNorm + ReLU
//   CTA: M=64 (32 paired channels) x N=512 (all L), K=256
//   512 threads (16 warps), warp grid 2(m) x 8(n), warp tile 32x64
//   BK=32, 3-stage cp.async
// ---------------------------------------------------------------------------
#define BK      32
#define STRIDE  80
#define A_SZ    (64 * STRIDE)            // 5120
#define B_SZ    (512 * STRIDE)           // 40960
#define STAGE_B (A_SZ + B_SZ)            // 46080
#define STAGES  3
#define GSMEM   (STAGES * STAGE_B)       // 138240
#define NKT     (KTOT / BK)              // 8
#define YSTR    520

__global__ __launch_bounds__(512, 1)
void gemm_kernel(const int* __restrict__ idx, float* __restrict__ out) {
    extern __shared__ char smem[];
    const uint32_t sb = s2u(smem);
    const int tid = threadIdx.x;
    const int wid = tid >> 5;
    const int lane = tid & 31;
    const int mt = blockIdx.x;           // 0..7
    const int b  = blockIdx.y;

    const int warp_m = wid & 1;          // 0..1 (32 rows)
    const int warp_n = wid >> 1;         // 0..7 (64 cols)

    const uint32_t a_lm = (uint32_t)(warp_m * 32 + (lane & 15)) * STRIDE + ((lane >> 4) * 16);
    const uint32_t b_lm = (uint32_t)(warp_n * 64 + (lane & 7) + ((lane >> 4) << 3)) * STRIDE
                        + (((lane >> 3) & 1) * 16);

    float acc[2][8][4];
#pragma unroll
    for (int i = 0; i < 2; i++)
#pragma unroll
        for (int j = 0; j < 8; j++)
#pragma unroll
            for (int k = 0; k < 4; k++) acc[i][j][k] = 0.f;

    auto load_tile = [&](int kt, int s) {
        const uint32_t base = sb + s * STAGE_B;
        if (tid < 256) {                  // A: 64 rows x 4 chunks
            int row = tid >> 2, c16 = tid & 3;
            const void* src = g_A + (size_t)(mt * 64 + row) * KTOT + kt * BK + c16 * 8;
            cpasync16(base + row * STRIDE + c16 * 16, src);
        }
#pragma unroll
        for (int i = 0; i < 4; i++) {     // B: 512 rows x 4 chunks = 2048
            int t = tid + i * 512;
            int row = t >> 2, c16 = t & 3;
            const void* src = g_xh + ((size_t)b * LSQ + row) * CCH + kt * BK + c16 * 8;
            cpasync16(base + A_SZ + row * STRIDE + c16 * 16, src);
        }
        cp_commit();
    };

    load_tile(0, 0);
    load_tile(1, 1);

    for (int kt = 0; kt < NKT; kt++) {
        const int s = kt % STAGES;
        cp_wait1();
        __syncthreads();
        if (kt + 2 < NKT) load_tile(kt + 2, (kt + 2) % STAGES);
        else cp_commit();

        const uint32_t abase = sb + s * STAGE_B + a_lm;
        const uint32_t bbase = sb + s * STAGE_B + A_SZ + b_lm;
#pragma unroll
        for (int k16 = 0; k16 < 2; k16++) {
            uint32_t af[2][4], bf[4][4];
#pragma unroll
            for (int mi = 0; mi < 2; mi++)
                ldm_x4(af[mi], abase + mi * 16 * STRIDE + k16 * 32);
#pragma unroll
            for (int bi = 0; bi < 4; bi++)
                ldm_x4(bf[bi], bbase + bi * 16 * STRIDE + k16 * 32);
#pragma unroll
            for (int mi = 0; mi < 2; mi++)
#pragma unroll
                for (int ni = 0; ni < 8; ni++)
                    mma_f16(acc[mi][ni], af[mi],
                            bf[ni >> 1][(ni & 1) * 2], bf[ni >> 1][(ni & 1) * 2 + 1]);
        }
        __syncthreads();
    }

    // ---------------- fused epilogue ----------------
    cp_wait0();
    __syncthreads();

    float* Y1s = (float*)smem;                  // [32][YSTR]
    float* Y2s = Y1s + 32 * YSTR;               // [32][YSTR]
    int*   idxs = (int*)(Y1s + 64 * YSTR);      // [512]

    float* Yw = (warp_m == 0) ? Y1s : Y2s;
    const int grp = lane >> 2, quad = lane & 3;
#pragma unroll
    for (int mi = 0; mi < 2; mi++) {
        int rr = mi * 16 + grp;
#pragma unroll
        for (int ni = 0; ni < 8; ni++) {
            int col = warp_n * 64 + ni * 8 + quad * 2;
            *(float2*)&Yw[(size_t)rr * YSTR + col] = make_float2(acc[mi][ni][0], acc[mi][ni][1]);
            *(float2*)&Yw[(size_t)(rr + 8) * YSTR + col] = make_float2(acc[mi][ni][2], acc[mi][ni][3]);
        }
    }
    idxs[tid] = idx[(size_t)b * LSQ + tid];
    __syncthreads();

    // 2 channels per warp (16 warps x 2 = 32 channels)
#pragma unroll
    for (int it = 0; it < 2; it++) {
        const int c = wid * 2 + it;
        const float* y1 = Y1s + (size_t)c * YSTR;
        const float* y2 = Y2s + (size_t)c * YSTR;
        float v[16];
        float s = 0.f, s2 = 0.f;
#pragma unroll
        for (int i = 0; i < 16; i++) {
            int l = lane + i * 32;
            int j = idxs[l];
            float g2 = (j < LSQ) ? y2[j] : 0.f;
            float y = y1[l] + g2;
            v[i] = y;
            s += y; s2 += y * y;
        }
#pragma unroll
        for (int o = 16; o > 0; o >>= 1) {
            s  += __shfl_xor_sync(0xffffffffu, s,  o);
            s2 += __shfl_xor_sync(0xffffffffu, s2, o);
        }
        const float inv_l = 1.0f / (float)LSQ;
        float mu  = s * inv_l;
        float var = s2 * inv_l - mu * mu;
        float rstd = rsqrtf(var + 1e-5f);

        float* o = out + ((size_t)b * CCH + mt * 32 + c) * LSQ;
#pragma unroll
        for (int i = 0; i < 16; i++) {
            int l = lane + i * 32;
            o[l] = fmaxf((v[i] - mu) * rstd, 0.f);
        }
    }
}

// ---------------------------------------------------------------------------
// launch
// ---------------------------------------------------------------------------
extern "C" void kernel_launch(void* const* d_in, const int* in_sizes, int n_in,
                              void* d_out, int out_size) {
    const float* x    = (const float*)d_in[0];   // [B, C, L]
    const int*   idx  = (const int*)d_in[1];     // [B, L]
    const float* W    = (const float*)d_in[2];   // [C, 2C] (bias cancels)
    float* out = (float*)d_out;

    cudaFuncSetAttribute(gemm_kernel, cudaFuncAttributeMaxDynamicSharedMemorySize, GSMEM);

    prep_kernel<<<(8 * 64 * KTOT + 255) / 256, 256>>>(W);

    dim3 cgrid(LSQ / 32, CCH / 128, BATCH);
    conv_kernel<<<cgrid, 256>>>(x);

    dim3 ggrid(8, BATCH);
    gemm_kernel<<<ggrid, 512, GSMEM>>>(idx, out);
}

// round 10
// speedup vs baseline: 1.0476x; 1.0476x over previous
#include <cuda_runtime.h>
#include <cuda_fp16.h>
#include <cstdint>

#define BATCH 256
#define CCH   256       // C
#define LSQ   512       // L
#define TWOC  512       // 2C
#define KTOT  256

// ---------------------------------------------------------------------------
// Device scratch
// ---------------------------------------------------------------------------
// A paired per m-tile: [8][64][256]; rows r<32 -> W1 ch mt*32+r, r>=32 -> W2 same ch
__device__ __half  g_A[8 * 64 * KTOT];                  // 256 KB
__device__ __half  g_xh[(size_t)BATCH * LSQ * CCH];     // 67 MB  [b, l, c]

// ---------------------------------------------------------------------------
// helpers
// ---------------------------------------------------------------------------
__device__ __forceinline__ uint32_t s2u(const void* p) {
    uint32_t a;
    asm("{ .reg .u64 t; cvta.to.shared.u64 t, %1; cvt.u32.u64 %0, t; }" : "=r"(a) : "l"(p));
    return a;
}
__device__ __forceinline__ void cpasync16(uint32_t dst, const void* src) {
    asm volatile("cp.async.cg.shared.global [%0], [%1], 16;" :: "r"(dst), "l"(src) : "memory");
}
__device__ __forceinline__ void cp_commit() {
    asm volatile("cp.async.commit_group;" ::: "memory");
}
__device__ __forceinline__ void cp_wait1() {
    asm volatile("cp.async.wait_group 1;" ::: "memory");
}
__device__ __forceinline__ void cp_wait0() {
    asm volatile("cp.async.wait_group 0;" ::: "memory");
}
__device__ __forceinline__ void ldm_x4(uint32_t* r, uint32_t addr) {
    asm volatile("ldmatrix.sync.aligned.m8n8.x4.shared.b16 {%0,%1,%2,%3}, [%4];"
                 : "=r"(r[0]), "=r"(r[1]), "=r"(r[2]), "=r"(r[3]) : "r"(addr));
}
__device__ __forceinline__ void mma_f16(float* c, const uint32_t* a, uint32_t b0, uint32_t b1) {
    asm volatile(
        "mma.sync.aligned.m16n8k16.row.col.f32.f16.f16.f32 "
        "{%0,%1,%2,%3}, {%4,%5,%6,%7}, {%8,%9}, {%0,%1,%2,%3};"
        : "+f"(c[0]), "+f"(c[1]), "+f"(c[2]), "+f"(c[3])
        : "r"(a[0]), "r"(a[1]), "r"(a[2]), "r"(a[3]), "r"(b0), "r"(b1));
}

// ---------------------------------------------------------------------------
// Kernel 1: pack A paired  [8][64][256] fp16
// ---------------------------------------------------------------------------
__global__ void prep_kernel(const float* __restrict__ W) {
    int i = blockIdx.x * blockDim.x + threadIdx.x;
    if (i >= 8 * 64 * KTOT) return;
    int t = i >> 14;
    int r = (i >> 8) & 63;
    int k = i & 255;
    int ch = t * 32 + (r & 31);
    float w = (r < 32) ? W[ch * TWOC + k] : W[ch * TWOC + CCH + k];
    g_A[i] = __float2half(w);
}

// ---------------------------------------------------------------------------
// Kernel 2: transpose + convert x[b,c,l] f32 -> xh[b,l,c] fp16
// ---------------------------------------------------------------------------
__global__ __launch_bounds__(256)
void conv_kernel(const float* __restrict__ x) {
    __shared__ float tile[128][33];
    int b  = blockIdx.z;
    int l0 = blockIdx.x * 32;
    int c0 = blockIdx.y * 128;
    int lane = threadIdx.x & 31, w = threadIdx.x >> 5;

    const float* xb = x + ((size_t)b * CCH + c0) * LSQ + l0;
#pragma unroll
    for (int i = 0; i < 16; i++) {
        int c = w + i * 8;
        tile[c][lane] = xb[(size_t)c * LSQ + lane];
    }
    __syncthreads();

#pragma unroll
    for (int i = 0; i < 4; i++) {
        int l = w + i * 8;
        int c4 = lane * 4;
        __half2 h01 = __floats2half2_rn(tile[c4 + 0][l], tile[c4 + 1][l]);
        __half2 h23 = __floats2half2_rn(tile[c4 + 2][l], tile[c4 + 3][l]);
        size_t o = ((size_t)b * LSQ + l0 + l) * CCH + c0 + c4;
        *(uint2*)(g_xh + o) = make_uint2(*(uint32_t*)&h01, *(uint32_t*)&h23);
    }
}

// ---------------------------------------------------------------------------
// Kernel 3: fused GEMM + gather + InstanceNorm + ReLU
//   CTA: M=64 x N=512, K=256, BK=64, 2-stage cp.async
//   512 threads (16 warps), warp grid 2(m) x 8(n), warp tile 32x64
// ---------------------------------------------------------------------------
#define BK      64
#define STRIDE  144
#define A_SZ    (64 * STRIDE)            // 9216
#define B_SZ    (512 * STRIDE)           // 73728
#define STAGE_B (A_SZ + B_SZ)            // 82944
#define STAGES  2
#define GSMEM   (STAGES * STAGE_B)       // 165888
#define NKT     (KTOT / BK)              // 4
#define YSTR    520

__global__ __launch_bounds__(512, 1)
void gemm_kernel(const int* __restrict__ idx, float* __restrict__ out) {
    extern __shared__ char smem[];
    const uint32_t sb = s2u(smem);
    const int tid = threadIdx.x;
    const int wid = tid >> 5;
    const int lane = tid & 31;
    const int mt = blockIdx.x;           // 0..7
    const int b  = blockIdx.y;

    const int warp_m = wid & 1;          // 0..1 (32 rows)
    const int warp_n = wid >> 1;         // 0..7 (64 cols)

    const uint32_t a_lm = (uint32_t)(warp_m * 32 + (lane & 15)) * STRIDE + ((lane >> 4) * 16);
    const uint32_t b_lm = (uint32_t)(warp_n * 64 + (lane & 7) + ((lane >> 4) << 3)) * STRIDE
                        + (((lane >> 3) & 1) * 16);

    float acc[2][8][4];
#pragma unroll
    for (int i = 0; i < 2; i++)
#pragma unroll
        for (int j = 0; j < 8; j++)
#pragma unroll
            for (int k = 0; k < 4; k++) acc[i][j][k] = 0.f;

    auto load_tile = [&](int kt, int s) {
        const uint32_t base = sb + s * STAGE_B;
        // A: 64 rows x 8 chunks = 512 -> tid<512 one each
        {
            int row = tid >> 3, c16 = tid & 7;
            const void* src = g_A + (size_t)(mt * 64 + row) * KTOT + kt * BK + c16 * 8;
            cpasync16(base + row * STRIDE + c16 * 16, src);
        }
        // B: 512 rows x 8 chunks = 4096 -> 8 per thread
#pragma unroll
        for (int i = 0; i < 8; i++) {
            int t = tid + i * 512;
            int row = t >> 3, c16 = t & 7;
            const void* src = g_xh + ((size_t)b * LSQ + row) * CCH + kt * BK + c16 * 8;
            cpasync16(base + A_SZ + row * STRIDE + c16 * 16, src);
        }
        cp_commit();
    };

    load_tile(0, 0);
    load_tile(1, 1);

    for (int kt = 0; kt < NKT; kt++) {
        const int s = kt & 1;
        if (kt == NKT - 1) cp_wait0(); else cp_wait1();
        __syncthreads();

        const uint32_t abase = sb + s * STAGE_B + a_lm;
        const uint32_t bbase = sb + s * STAGE_B + A_SZ + b_lm;
#pragma unroll
        for (int k16 = 0; k16 < 4; k16++) {
            uint32_t af[2][4], bf[4][4];
#pragma unroll
            for (int mi = 0; mi < 2; mi++)
                ldm_x4(af[mi], abase + mi * 16 * STRIDE + k16 * 32);
#pragma unroll
            for (int bi = 0; bi < 4; bi++)
                ldm_x4(bf[bi], bbase + bi * 16 * STRIDE + k16 * 32);
#pragma unroll
            for (int mi = 0; mi < 2; mi++)
#pragma unroll
                for (int ni = 0; ni < 8; ni++)
                    mma_f16(acc[mi][ni], af[mi],
                            bf[ni >> 1][(ni & 1) * 2], bf[ni >> 1][(ni & 1) * 2 + 1]);
        }
        __syncthreads();
        if (kt + 2 < NKT) load_tile(kt + 2, s);
    }

    // ---------------- fused epilogue ----------------
    float* Y1s = (float*)smem;                  // [32][YSTR]
    float* Y2s = Y1s + 32 * YSTR;               // [32][YSTR]
    int*   idxs = (int*)(Y1s + 64 * YSTR);      // [512]

    float* Yw = (warp_m == 0) ? Y1s : Y2s;
    const int grp = lane >> 2, quad = lane & 3;
#pragma unroll
    for (int mi = 0; mi < 2; mi++) {
        int rr = mi * 16 + grp;
#pragma unroll
        for (int ni = 0; ni < 8; ni++) {
            int col = warp_n * 64 + ni * 8 + quad * 2;
            *(float2*)&Yw[(size_t)rr * YSTR + col] = make_float2(acc[mi][ni][0], acc[mi][ni][1]);
            *(float2*)&Yw[(size_t)(rr + 8) * YSTR + col] = make_float2(acc[mi][ni][2], acc[mi][ni][3]);
        }
    }
    idxs[tid] = idx[(size_t)b * LSQ + tid];
    __syncthreads();

    // 2 channels per warp (16 warps x 2 = 32 channels)
#pragma unroll
    for (int it = 0; it < 2; it++) {
        const int c = wid * 2 + it;
        const float* y1 = Y1s + (size_t)c * YSTR;
        const float* y2 = Y2s + (size_t)c * YSTR;
        float v[16];
        float s = 0.f, s2 = 0.f;
#pragma unroll
        for (int i = 0; i < 16; i++) {
            int l = lane + i * 32;
            int j = idxs[l];
            float g2 = (j < LSQ) ? y2[j] : 0.f;
            float y = y1[l] + g2;
            v[i] = y;
            s += y; s2 += y * y;
        }
#pragma unroll
        for (int o = 16; o > 0; o >>= 1) {
            s  += __shfl_xor_sync(0xffffffffu, s,  o);
            s2 += __shfl_xor_sync(0xffffffffu, s2, o);
        }
        const float inv_l = 1.0f / (float)LSQ;
        float mu  = s * inv_l;
        float var = s2 * inv_l - mu * mu;
        float rstd = rsqrtf(var + 1e-5f);

        float* o = out + ((size_t)b * CCH + mt * 32 + c) * LSQ;
#pragma unroll
        for (int i = 0; i < 16; i++) {
            int l = lane + i * 32;
            o[l] = fmaxf((v[i] - mu) * rstd, 0.f);
        }
    }
}

// ---------------------------------------------------------------------------
// launch
// ---------------------------------------------------------------------------
extern "C" void kernel_launch(void* const* d_in, const int* in_sizes, int n_in,
                              void* d_out, int out_size) {
    const float* x    = (const float*)d_in[0];   // [B, C, L]
    const int*   idx  = (const int*)d_in[1];     // [B, L]
    const float* W    = (const float*)d_in[2];   // [C, 2C] (bias cancels)
    float* out = (float*)d_out;

    cudaFuncSetAttribute(gemm_kernel, cudaFuncAttributeMaxDynamicSharedMemorySize, GSMEM);

    prep_kernel<<<(8 * 64 * KTOT + 255) / 256, 256>>>(W);

    dim3 cgrid(LSQ / 32, CCH / 128, BATCH);
    conv_kernel<<<cgrid, 256>>>(x);

    dim3 ggrid(8, BATCH);
    gemm_kernel<<<ggrid, 512, GSMEM>>>(idx, out);
}